// round 11
// baseline (speedup 1.0000x reference)
#include <cuda_runtime.h>
#include <cuda_bf16.h>
#include <cstdint>

// ---------------------------------------------------------------------------
// VectorQuantizer: N=16384 queries, D=256, K=8192 codes.
// d_out (fp32): [0,4194304) quantized STE NCHW; [+16384) indices; [last] loss.
//
// mma.sync (bf16, fp32 acc) distance GEMM with fused running-min + candidate
// collection; exact fp64 rescore of ALL candidates reproduces the reference
// fp32 argmin (incl. first-index ties). All gather indices hard-clamped.
// (tcgen05 unavailable: harness PTX target is compute_103, not sm_103a.)
// ---------------------------------------------------------------------------

#define NQ   16384
#define KC   8192
#define DIM  256
#define BQ   128

#define QUANT_ELEMS (NQ * DIM)
#define IDX_OFF     QUANT_ELEMS
#define LOSS_OFF    (QUANT_ELEMS + NQ)

#define EPS_SEL 4.0e-4f
#define CAP     256

// ---- device scratch (no cudaMalloc allowed) -------------------------------
__device__ __align__(256) __nv_bfloat16 g_Abf[NQ * DIM];   // [q][d] 8MB
__device__ __align__(256) __nv_bfloat16 g_Bbf[KC * DIM];   // [k][d] 4MB
__device__ float  g_cn[KC];
__device__ float2 g_cand[(size_t)NQ * CAP];                // (dist, k) 32MB
__device__ int    g_ccnt[NQ];
__device__ int    g_fin[NQ];
__device__ float  g_loss;

// ============================ PTX helpers ==================================
__device__ __forceinline__ uint32_t smem_u32(const void* p) {
    uint32_t a;
    asm("{ .reg .u64 t; cvta.to.shared.u64 t, %1; cvt.u32.u64 %0, t; }"
        : "=r"(a) : "l"(p));
    return a;
}

#define CP_ASYNC16(dst, src) \
    asm volatile("cp.async.cg.shared.global [%0], [%1], 16;" \
        :: "r"((uint32_t)(dst)), "l"(src) : "memory")
#define CP_ASYNC_COMMIT() asm volatile("cp.async.commit_group;" ::: "memory")
#define CP_ASYNC_WAIT(n)  asm volatile("cp.async.wait_group %0;" :: "n"(n) : "memory")

#define LDSM_X4(r0, r1, r2, r3, addr) \
    asm volatile("ldmatrix.sync.aligned.m8n8.x4.shared.b16 {%0,%1,%2,%3}, [%4];" \
        : "=r"(r0), "=r"(r1), "=r"(r2), "=r"(r3) : "r"(addr))

#define MMA16816(c, a, b0, b1) \
    asm volatile("mma.sync.aligned.m16n8k16.row.col.f32.bf16.bf16.f32 " \
        "{%0,%1,%2,%3}, {%4,%5,%6,%7}, {%8,%9}, {%0,%1,%2,%3};" \
        : "+f"((c)[0]), "+f"((c)[1]), "+f"((c)[2]), "+f"((c)[3]) \
        : "r"((a)[0]), "r"((a)[1]), "r"((a)[2]), "r"((a)[3]), \
          "r"(b0), "r"(b1))

// order-preserving float<->uint for atomicMin
__device__ __forceinline__ uint32_t enc_f(float f) {
    uint32_t u = __float_as_uint(f);
    return (u & 0x80000000u) ? ~u : (u | 0x80000000u);
}
__device__ __forceinline__ float dec_f(uint32_t u) {
    return __uint_as_float((u & 0x80000000u) ? (u ^ 0x80000000u) : ~u);
}

// XOR-swizzled smem addr: tile rows of 512B (32 x 16B granules)
__device__ __forceinline__ uint32_t swz(uint32_t base, int r, int g) {
    return base + r * 512 + ((g ^ (r & 7)) << 4);
}

// SMEM layout (dynamic): A 64KB, B 2x64KB, rowmin 512B, cnt 512B
#define A_OFF      0
#define B_OFF      65536
#define ROWMIN_OFF 196608
#define CNT_OFF    197120
#define SMEM_SZ    197632

// ============================ prep kernels =================================
__global__ void zero_loss_kernel() { g_loss = 0.0f; }

__device__ __forceinline__ uint32_t pack_bf2(float a, float b) {
    __nv_bfloat162 h = __floats2bfloat162_rn(a, b);
    return *reinterpret_cast<uint32_t*>(&h);
}

// hidden [16][256][1024] fp32 -> g_Abf [q=b*1024+hw][d] bf16
__global__ void conv_hidden(const float* __restrict__ hidden) {
    __shared__ float t[32][33];
    const int hw0 = blockIdx.x * 32, d0 = blockIdx.y * 32, b = blockIdx.z;
    const int tx = threadIdx.x, ty = threadIdx.y;     // (32, 8)
#pragma unroll
    for (int r = 0; r < 4; r++)
        t[ty + 8 * r][tx] =
            hidden[(((size_t)b * 256 + d0 + ty + 8 * r) << 10) + hw0 + tx];
    __syncthreads();
#pragma unroll
    for (int r = 0; r < 4; r++)
        g_Abf[(size_t)(b * 1024 + hw0 + ty + 8 * r) * DIM + d0 + tx] =
            __float2bfloat16(t[tx][ty + 8 * r]);
}

// cb [8192][256] fp32 -> g_Bbf bf16 + g_cn fp32. One warp per code row.
__global__ void conv_cb(const float* __restrict__ cb) {
    const int w = threadIdx.x >> 5, lane = threadIdx.x & 31;
    const int k = blockIdx.x * 8 + w;
    const float4* row = (const float4*)(cb + (size_t)k * DIM);
    float4 a = row[lane * 2], b2 = row[lane * 2 + 1];
    uint4 o;
    o.x = pack_bf2(a.x, a.y);  o.y = pack_bf2(a.z, a.w);
    o.z = pack_bf2(b2.x, b2.y); o.w = pack_bf2(b2.z, b2.w);
    *(uint4*)(g_Bbf + (size_t)k * DIM + lane * 8) = o;
    float s = a.x*a.x + a.y*a.y + a.z*a.z + a.w*a.w
            + b2.x*b2.x + b2.y*b2.y + b2.z*b2.z + b2.w*b2.w;
#pragma unroll
    for (int off = 16; off > 0; off >>= 1) s += __shfl_xor_sync(~0u, s, off);
    if (lane == 0) g_cn[k] = s;
}

// ============================ main kernel ==================================
// 8 warps (2x4): warp tile 64m x 32n; CTA = 128 queries x 128-code chunks,
// K=256 accumulated per chunk; 64 chunks. Fused min + candidate collection.
__global__ void __launch_bounds__(256, 1)
vq_main() {
    extern __shared__ char sm[];
    const uint32_t sb = smem_u32(sm);
    const int tid = threadIdx.x;
    const int wid = tid >> 5, lane = tid & 31;
    const int wm = wid >> 2, wn = wid & 3;
    const int qbase = blockIdx.x * BQ;

    uint32_t* rowmin_s = (uint32_t*)(sm + ROWMIN_OFF);
    uint32_t* cnt_s    = (uint32_t*)(sm + CNT_OFF);
    if (tid < 128) { rowmin_s[tid] = enc_f(3.4e38f); cnt_s[tid] = 0; }

    // ---- group 0: A tile + B chunk 0 (cp.async, swizzled) ----
    {
        const char* asrc = (const char*)(g_Abf + (size_t)qbase * DIM);
#pragma unroll
        for (int it = 0; it < 16; it++) {
            int idx = it * 256 + tid;                 // 4096 granules
            int r = idx >> 5, g = idx & 31;
            CP_ASYNC16(swz(sb + A_OFF, r, g), asrc + (size_t)idx * 16);
        }
        const char* bsrc = (const char*)g_Bbf;        // chunk 0
#pragma unroll
        for (int it = 0; it < 16; it++) {
            int idx = it * 256 + tid;
            int r = idx >> 5, g = idx & 31;
            CP_ASYNC16(swz(sb + B_OFF, r, g), bsrc + (size_t)idx * 16);
        }
        CP_ASYNC_COMMIT();
    }
    __syncthreads();   // rowmin/cnt init visible

    for (int c = 0; c < 64; c++) {
        const int buf = c & 1;
        if (c + 1 < 64) {
            const char* bsrc = (const char*)(g_Bbf + (size_t)(c + 1) * 128 * DIM);
            const uint32_t bb = sb + B_OFF + ((c + 1) & 1) * 65536;
#pragma unroll
            for (int it = 0; it < 16; it++) {
                int idx = it * 256 + tid;
                int r = idx >> 5, g = idx & 31;
                CP_ASYNC16(swz(bb, r, g), bsrc + (size_t)idx * 16);
            }
            CP_ASYNC_COMMIT();
            CP_ASYNC_WAIT(1);
        } else {
            CP_ASYNC_WAIT(0);
        }
        __syncthreads();

        // cn for this thread's 8 columns of the chunk
        const int kcol0 = c * 128 + wn * 32 + 2 * (lane & 3);
        float cnr[8];
#pragma unroll
        for (int nt = 0; nt < 4; nt++) {
            cnr[nt * 2]     = __ldg(g_cn + kcol0 + nt * 8);
            cnr[nt * 2 + 1] = __ldg(g_cn + kcol0 + nt * 8 + 1);
        }

        float acc[4][4][4];
#pragma unroll
        for (int mt = 0; mt < 4; mt++)
#pragma unroll
            for (int nt = 0; nt < 4; nt++)
#pragma unroll
                for (int j = 0; j < 4; j++) acc[mt][nt][j] = 0.0f;

        const uint32_t aBase = sb + A_OFF;
        const uint32_t bBase = sb + B_OFF + buf * 65536;
        const int lr = lane & 15, lg = lane >> 4;

#pragma unroll
        for (int ks = 0; ks < 16; ks++) {
            uint32_t a[4][4];
#pragma unroll
            for (int mt = 0; mt < 4; mt++) {
                int r = wm * 64 + mt * 16 + lr;
                LDSM_X4(a[mt][0], a[mt][1], a[mt][2], a[mt][3],
                        swz(aBase, r, 2 * ks + lg));
            }
            uint32_t b[2][4];
#pragma unroll
            for (int bt = 0; bt < 2; bt++) {
                int r = wn * 32 + bt * 16 + lr;
                LDSM_X4(b[bt][0], b[bt][1], b[bt][2], b[bt][3],
                        swz(bBase, r, 2 * ks + lg));
            }
#pragma unroll
            for (int mt = 0; mt < 4; mt++)
#pragma unroll
                for (int nt = 0; nt < 4; nt++) {
                    int bt = nt >> 1, hi = nt & 1;
                    MMA16816(acc[mt][nt], a[mt], b[bt][hi], b[bt][hi + 2]);
                }
        }

        // ---- fused epilogue: dist = cn - 2*dot; band-collect candidates ----
#pragma unroll
        for (int mt = 0; mt < 4; mt++) {
#pragma unroll
            for (int half = 0; half < 2; half++) {
                const int row = wm * 64 + mt * 16 + (lane >> 2) + 8 * half;
                float d[8];
                float dmin = 3.4e38f;
#pragma unroll
                for (int nt = 0; nt < 4; nt++) {
#pragma unroll
                    for (int j = 0; j < 2; j++) {
                        float v = fmaf(-2.0f, acc[mt][nt][2 * half + j],
                                       cnr[nt * 2 + j]);
                        d[nt * 2 + j] = v;
                        dmin = fminf(dmin, v);
                    }
                }
                float curf = dec_f(rowmin_s[row]);
                if (dmin <= curf + EPS_SEL) {          // rare
                    float thr = curf + EPS_SEL;
                    float2* cs = g_cand + (size_t)(qbase + row) * CAP;
#pragma unroll
                    for (int i = 0; i < 8; i++) {
                        if (d[i] <= thr) {
                            int nt = i >> 1, j = i & 1;
                            int k = c * 128 + wn * 32 + nt * 8 +
                                    2 * (lane & 3) + j;
                            uint32_t slot = atomicAdd(&cnt_s[row], 1u);
                            if (slot < CAP)
                                cs[slot] = make_float2(d[i], __int_as_float(k));
                        }
                    }
                    if (dmin < curf) atomicMin(&rowmin_s[row], enc_f(dmin));
                }
            }
        }
        __syncthreads();
    }

    if (tid < 128) {
        uint32_t n = cnt_s[tid];
        if (n == 0) {                                  // paranoia: never empty
            g_cand[(size_t)(qbase + tid) * CAP] =
                make_float2(0.0f, __int_as_float(0));
            n = 1;
        }
        g_ccnt[qbase + tid] = n < CAP ? (int)n : CAP;
    }
}

// ============================ rescore ======================================
// Warp per query: exact fp64 rescore of ALL stored candidates with the
// reference's fp32 rounding R = f32(f32(fnorm - 2 dot) + cn); (R, k) lex min.
// Including extra candidates is strictly faithful (same R, smaller k would
// also win the reference's first-min scan). k hard-clamped before deref.
__global__ void __launch_bounds__(256)
vq_rescore(const float* __restrict__ hidden, const float* __restrict__ cb,
           float* __restrict__ out) {
    const int w = threadIdx.x >> 5, lane = threadIdx.x & 31;
    const int q = blockIdx.x * 8 + w;

    const int b = q >> 10, hw = q & 1023;
    const float* xcol = hidden + (size_t)b * (DIM * 1024) + hw;
    float xr[8];
    double fn = 0.0;
#pragma unroll
    for (int t = 0; t < 8; t++) {
        float v = xcol[(size_t)(lane * 8 + t) * 1024];
        xr[t] = v;
        fn += (double)v * (double)v;
    }
#pragma unroll
    for (int o = 16; o > 0; o >>= 1) fn += __shfl_xor_sync(~0u, fn, o);
    const float fn32 = (float)fn;

    int cnt = g_ccnt[q];
    if (cnt < 0) cnt = 0;
    if (cnt > CAP) cnt = CAP;
    const float2* cands = g_cand + (size_t)q * CAP;

    float bestR = 3.4e38f;
    int bestK = 0;
    for (int c = 0; c < cnt; c++) {
        int k = __float_as_int(cands[c].y) & (KC - 1);   // hard clamp
        const float4* er = (const float4*)(cb + (size_t)k * DIM + lane * 8);
        float4 e0 = er[0], e1 = er[1];
        float ev[8] = {e0.x, e0.y, e0.z, e0.w, e1.x, e1.y, e1.z, e1.w};
        double dot = 0.0, cnd = 0.0;
#pragma unroll
        for (int t = 0; t < 8; t++) {
            double ed = (double)ev[t];
            dot += (double)xr[t] * ed;
            cnd += ed * ed;
        }
#pragma unroll
        for (int o = 16; o > 0; o >>= 1) {
            dot += __shfl_xor_sync(~0u, dot, o);
            cnd += __shfl_xor_sync(~0u, cnd, o);
        }
        float t1 = __fsub_rn(fn32, __fmul_rn(2.0f, (float)dot));
        float R  = __fadd_rn(t1, (float)cnd);
        if (R < bestR || (R == bestR && k < bestK)) { bestR = R; bestK = k; }
    }
    if (lane == 0) {
        g_fin[q] = bestK;
        out[IDX_OFF + q] = (float)bestK;
    }
}

// ============================ output + loss ================================
__global__ void __launch_bounds__(256)
vq_output(const float* __restrict__ hidden, const float* __restrict__ cb,
          float* __restrict__ out) {
    __shared__ float Es[64 * 129];
    __shared__ int s_fin[128];
    __shared__ float lred[256];

    const int tid = threadIdx.x;
    const int qbase = blockIdx.x * BQ;
    const int b = qbase >> 10, hwbase = qbase & 1023;

    if (tid < 128) s_fin[tid] = g_fin[qbase + tid] & (KC - 1);   // hard clamp
    __syncthreads();

    const float* hsrc = hidden + (size_t)b * (DIM * 1024) + hwbase;
    float* obase = out + (size_t)b * (DIM * 1024) + hwbase;

    float lsum = 0.0f;
    for (int dchunk = 0; dchunk < 4; dchunk++) {
        const int dbase = dchunk * 64;
        for (int i = tid; i < 128 * 64; i += 256) {
            int qq = i >> 6, dd = i & 63;
            Es[dd * 129 + qq] = cb[(size_t)s_fin[qq] * DIM + dbase + dd];
        }
        __syncthreads();
        for (int i = tid; i < 64 * 128; i += 256) {
            int dd = i >> 7, qq = i & 127;
            int d = dbase + dd;
            float x = hsrc[(d << 10) + qq];
            float e = Es[dd * 129 + qq];
            float df = __fsub_rn(e, x);
            lsum += df * df;
            obase[(d << 10) + qq] = __fadd_rn(x, df);   // STE rounding
        }
        __syncthreads();
    }

    lred[tid] = lsum;
    __syncthreads();
    for (int s = 128; s > 0; s >>= 1) {
        if (tid < s) lred[tid] += lred[tid + s];
        __syncthreads();
    }
    if (tid == 0) atomicAdd(&g_loss, lred[0]);
}

__global__ void finalize_loss(float* __restrict__ out) {
    out[LOSS_OFF] = 1.25f * g_loss / (float)(NQ * DIM);
}

// ---------------------------------------------------------------------------
extern "C" void kernel_launch(void* const* d_in, const int* in_sizes, int n_in,
                              void* d_out, int out_size) {
    const float* hidden = (const float*)d_in[0];
    const float* cb     = (const float*)d_in[1];
    if (n_in >= 2 && in_sizes[0] == KC * DIM) {   // defensive input-order swap
        const float* t = hidden; hidden = cb; cb = t;
    }
    float* out = (float*)d_out;

    cudaFuncSetAttribute(vq_main, cudaFuncAttributeMaxDynamicSharedMemorySize,
                         SMEM_SZ);

    zero_loss_kernel<<<1, 1>>>();
    conv_hidden<<<dim3(32, 8, 16), dim3(32, 8)>>>(hidden);
    conv_cb<<<KC / 8, 256>>>(cb);
    vq_main<<<NQ / BQ, 256, SMEM_SZ>>>();
    vq_rescore<<<NQ / 8, 256>>>(hidden, cb, out);
    vq_output<<<NQ / BQ, 256>>>(hidden, cb, out);
    finalize_loss<<<1, 1>>>(out);
}

// round 12
// speedup vs baseline: 7.3496x; 7.3496x over previous
#include <cuda_runtime.h>
#include <cuda_bf16.h>
#include <cstdint>

// ---------------------------------------------------------------------------
// VectorQuantizer: N=16384 queries, D=256, K=8192 codes.
// d_out (fp32): [0,4194304) quantized STE NCHW; [+16384) indices; [last] loss.
//
// mma.sync (bf16, fp32 acc) distance GEMM with fused two-phase running-min +
// candidate collection (phase A: min update; sync; phase B: collect with the
// fresh min -> ~12 candidates/query). Exact fp64 rescore of ALL candidates
// reproduces the reference fp32 argmin (incl. first-index ties).
// ---------------------------------------------------------------------------

#define NQ   16384
#define KC   8192
#define DIM  256
#define BQ   128

#define QUANT_ELEMS (NQ * DIM)
#define IDX_OFF     QUANT_ELEMS
#define LOSS_OFF    (QUANT_ELEMS + NQ)

#define EPS_SEL 4.0e-4f
#define CAP     256

// ---- device scratch (no cudaMalloc allowed) -------------------------------
__device__ __align__(256) __nv_bfloat16 g_Abf[NQ * DIM];   // [q][d] 8MB
__device__ __align__(256) __nv_bfloat16 g_Bbf[KC * DIM];   // [k][d] 4MB
__device__ float  g_cn[KC];
__device__ float2 g_cand[(size_t)NQ * CAP];                // (dist, k) 32MB
__device__ int    g_ccnt[NQ];
__device__ int    g_fin[NQ];
__device__ float  g_loss;

// ============================ PTX helpers ==================================
__device__ __forceinline__ uint32_t smem_u32(const void* p) {
    uint32_t a;
    asm("{ .reg .u64 t; cvta.to.shared.u64 t, %1; cvt.u32.u64 %0, t; }"
        : "=r"(a) : "l"(p));
    return a;
}

#define CP_ASYNC16(dst, src) \
    asm volatile("cp.async.cg.shared.global [%0], [%1], 16;" \
        :: "r"((uint32_t)(dst)), "l"(src) : "memory")
#define CP_ASYNC_COMMIT() asm volatile("cp.async.commit_group;" ::: "memory")
#define CP_ASYNC_WAIT(n)  asm volatile("cp.async.wait_group %0;" :: "n"(n) : "memory")

#define LDSM_X4(r0, r1, r2, r3, addr) \
    asm volatile("ldmatrix.sync.aligned.m8n8.x4.shared.b16 {%0,%1,%2,%3}, [%4];" \
        : "=r"(r0), "=r"(r1), "=r"(r2), "=r"(r3) : "r"(addr))

#define MMA16816(c, a, b0, b1) \
    asm volatile("mma.sync.aligned.m16n8k16.row.col.f32.bf16.bf16.f32 " \
        "{%0,%1,%2,%3}, {%4,%5,%6,%7}, {%8,%9}, {%0,%1,%2,%3};" \
        : "+f"((c)[0]), "+f"((c)[1]), "+f"((c)[2]), "+f"((c)[3]) \
        : "r"((a)[0]), "r"((a)[1]), "r"((a)[2]), "r"((a)[3]), \
          "r"(b0), "r"(b1))

// order-preserving float<->uint for atomicMin
__device__ __forceinline__ uint32_t enc_f(float f) {
    uint32_t u = __float_as_uint(f);
    return (u & 0x80000000u) ? ~u : (u | 0x80000000u);
}
__device__ __forceinline__ float dec_f(uint32_t u) {
    return __uint_as_float((u & 0x80000000u) ? (u ^ 0x80000000u) : ~u);
}

// XOR-swizzled smem addr: tile rows of 512B (32 x 16B granules)
__device__ __forceinline__ uint32_t swz(uint32_t base, int r, int g) {
    return base + r * 512 + ((g ^ (r & 7)) << 4);
}

// SMEM layout (dynamic): A 64KB, B 2x64KB, rowmin 512B, cnt 512B
#define A_OFF      0
#define B_OFF      65536
#define ROWMIN_OFF 196608
#define CNT_OFF    197120
#define SMEM_SZ    197632

// ============================ prep kernels =================================
__global__ void zero_loss_kernel() { g_loss = 0.0f; }

__device__ __forceinline__ uint32_t pack_bf2(float a, float b) {
    __nv_bfloat162 h = __floats2bfloat162_rn(a, b);
    return *reinterpret_cast<uint32_t*>(&h);
}

// hidden [16][256][1024] fp32 -> g_Abf [q=b*1024+hw][d] bf16
__global__ void conv_hidden(const float* __restrict__ hidden) {
    __shared__ float t[32][33];
    const int hw0 = blockIdx.x * 32, d0 = blockIdx.y * 32, b = blockIdx.z;
    const int tx = threadIdx.x, ty = threadIdx.y;     // (32, 8)
#pragma unroll
    for (int r = 0; r < 4; r++)
        t[ty + 8 * r][tx] =
            hidden[(((size_t)b * 256 + d0 + ty + 8 * r) << 10) + hw0 + tx];
    __syncthreads();
#pragma unroll
    for (int r = 0; r < 4; r++)
        g_Abf[(size_t)(b * 1024 + hw0 + ty + 8 * r) * DIM + d0 + tx] =
            __float2bfloat16(t[tx][ty + 8 * r]);
}

// cb [8192][256] fp32 -> g_Bbf bf16 + g_cn fp32. One warp per code row.
__global__ void conv_cb(const float* __restrict__ cb) {
    const int w = threadIdx.x >> 5, lane = threadIdx.x & 31;
    const int k = blockIdx.x * 8 + w;
    const float4* row = (const float4*)(cb + (size_t)k * DIM);
    float4 a = row[lane * 2], b2 = row[lane * 2 + 1];
    uint4 o;
    o.x = pack_bf2(a.x, a.y);  o.y = pack_bf2(a.z, a.w);
    o.z = pack_bf2(b2.x, b2.y); o.w = pack_bf2(b2.z, b2.w);
    *(uint4*)(g_Bbf + (size_t)k * DIM + lane * 8) = o;
    float s = a.x*a.x + a.y*a.y + a.z*a.z + a.w*a.w
            + b2.x*b2.x + b2.y*b2.y + b2.z*b2.z + b2.w*b2.w;
#pragma unroll
    for (int off = 16; off > 0; off >>= 1) s += __shfl_xor_sync(~0u, s, off);
    if (lane == 0) g_cn[k] = s;
}

// ============================ main kernel ==================================
// 8 warps (2x4): warp tile 64m x 32n; CTA = 128 queries x 128-code chunks,
// K=256 accumulated per chunk; 64 chunks. Two-phase fused min + collection.
__global__ void __launch_bounds__(256, 1)
vq_main() {
    extern __shared__ char sm[];
    const uint32_t sb = smem_u32(sm);
    const int tid = threadIdx.x;
    const int wid = tid >> 5, lane = tid & 31;
    const int wm = wid >> 2, wn = wid & 3;
    const int qbase = blockIdx.x * BQ;

    uint32_t* rowmin_s = (uint32_t*)(sm + ROWMIN_OFF);
    uint32_t* cnt_s    = (uint32_t*)(sm + CNT_OFF);
    if (tid < 128) { rowmin_s[tid] = enc_f(3.4e38f); cnt_s[tid] = 0; }

    // ---- group 0: A tile + B chunk 0 (cp.async, swizzled) ----
    {
        const char* asrc = (const char*)(g_Abf + (size_t)qbase * DIM);
#pragma unroll
        for (int it = 0; it < 16; it++) {
            int idx = it * 256 + tid;                 // 4096 granules
            int r = idx >> 5, g = idx & 31;
            CP_ASYNC16(swz(sb + A_OFF, r, g), asrc + (size_t)idx * 16);
        }
        const char* bsrc = (const char*)g_Bbf;        // chunk 0
#pragma unroll
        for (int it = 0; it < 16; it++) {
            int idx = it * 256 + tid;
            int r = idx >> 5, g = idx & 31;
            CP_ASYNC16(swz(sb + B_OFF, r, g), bsrc + (size_t)idx * 16);
        }
        CP_ASYNC_COMMIT();
    }
    __syncthreads();   // rowmin/cnt init visible

    for (int c = 0; c < 64; c++) {
        const int buf = c & 1;
        if (c + 1 < 64) {
            const char* bsrc = (const char*)(g_Bbf + (size_t)(c + 1) * 128 * DIM);
            const uint32_t bb = sb + B_OFF + ((c + 1) & 1) * 65536;
#pragma unroll
            for (int it = 0; it < 16; it++) {
                int idx = it * 256 + tid;
                int r = idx >> 5, g = idx & 31;
                CP_ASYNC16(swz(bb, r, g), bsrc + (size_t)idx * 16);
            }
            CP_ASYNC_COMMIT();
            CP_ASYNC_WAIT(1);
        } else {
            CP_ASYNC_WAIT(0);
        }
        __syncthreads();

        // cn for this thread's 8 columns of the chunk
        const int kcol0 = c * 128 + wn * 32 + 2 * (lane & 3);
        float cnr[8];
#pragma unroll
        for (int nt = 0; nt < 4; nt++) {
            cnr[nt * 2]     = __ldg(g_cn + kcol0 + nt * 8);
            cnr[nt * 2 + 1] = __ldg(g_cn + kcol0 + nt * 8 + 1);
        }

        float acc[4][4][4];
#pragma unroll
        for (int mt = 0; mt < 4; mt++)
#pragma unroll
            for (int nt = 0; nt < 4; nt++)
#pragma unroll
                for (int j = 0; j < 4; j++) acc[mt][nt][j] = 0.0f;

        const uint32_t aBase = sb + A_OFF;
        const uint32_t bBase = sb + B_OFF + buf * 65536;
        const int lr = lane & 15, lg = lane >> 4;

#pragma unroll
        for (int ks = 0; ks < 16; ks++) {
            uint32_t a[4][4];
#pragma unroll
            for (int mt = 0; mt < 4; mt++) {
                int r = wm * 64 + mt * 16 + lr;
                LDSM_X4(a[mt][0], a[mt][1], a[mt][2], a[mt][3],
                        swz(aBase, r, 2 * ks + lg));
            }
            uint32_t b[2][4];
#pragma unroll
            for (int bt = 0; bt < 2; bt++) {
                int r = wn * 32 + bt * 16 + lr;
                LDSM_X4(b[bt][0], b[bt][1], b[bt][2], b[bt][3],
                        swz(bBase, r, 2 * ks + lg));
            }
#pragma unroll
            for (int mt = 0; mt < 4; mt++)
#pragma unroll
                for (int nt = 0; nt < 4; nt++) {
                    int bt = nt >> 1, hi = nt & 1;
                    MMA16816(acc[mt][nt], a[mt], b[bt][hi], b[bt][hi + 2]);
                }
        }

        // ---- phase A: per-row-segment mins -> shared running min ----------
#pragma unroll
        for (int mt = 0; mt < 4; mt++) {
#pragma unroll
            for (int half = 0; half < 2; half++) {
                const int row = wm * 64 + mt * 16 + (lane >> 2) + 8 * half;
                float dmin = 3.4e38f;
#pragma unroll
                for (int nt = 0; nt < 4; nt++)
#pragma unroll
                    for (int j = 0; j < 2; j++)
                        dmin = fminf(dmin,
                            fmaf(-2.0f, acc[mt][nt][2 * half + j],
                                 cnr[nt * 2 + j]));
                // stale read only gates the atomic; stale >= current, so a
                // genuinely new min always passes the guard.
                float curf = dec_f(rowmin_s[row]);
                if (dmin < curf) atomicMin(&rowmin_s[row], enc_f(dmin));
            }
        }
        __syncthreads();   // rowmin now includes ALL rows/warps of chunks <= c

        // ---- phase B: collect with the fresh (tight) threshold ------------
#pragma unroll
        for (int mt = 0; mt < 4; mt++) {
#pragma unroll
            for (int half = 0; half < 2; half++) {
                const int row = wm * 64 + mt * 16 + (lane >> 2) + 8 * half;
                const float thr = dec_f(rowmin_s[row]) + EPS_SEL;
                float2* cs = g_cand + (size_t)(qbase + row) * CAP;
#pragma unroll
                for (int nt = 0; nt < 4; nt++) {
#pragma unroll
                    for (int j = 0; j < 2; j++) {
                        float v = fmaf(-2.0f, acc[mt][nt][2 * half + j],
                                       cnr[nt * 2 + j]);
                        if (v <= thr) {                // rare (~12/query total)
                            int k = c * 128 + wn * 32 + nt * 8 +
                                    2 * (lane & 3) + j;
                            uint32_t slot = atomicAdd(&cnt_s[row], 1u);
                            if (slot < CAP)
                                cs[slot] = make_float2(v, __int_as_float(k));
                        }
                    }
                }
            }
        }
        __syncthreads();
    }

    if (tid < 128) {
        uint32_t n = cnt_s[tid];
        if (n == 0) {                                  // paranoia: never empty
            g_cand[(size_t)(qbase + tid) * CAP] =
                make_float2(0.0f, __int_as_float(0));
            n = 1;
        }
        g_ccnt[qbase + tid] = n < CAP ? (int)n : CAP;
    }
}

// ============================ rescore ======================================
// Warp per query: exact fp64 rescore of ALL stored candidates with the
// reference's fp32 rounding R = f32(f32(fnorm - 2 dot) + cn); (R, k) lex min.
// Including extra candidates is strictly faithful (same R, smaller k would
// also win the reference's first-min scan). k hard-clamped before deref.
__global__ void __launch_bounds__(256)
vq_rescore(const float* __restrict__ hidden, const float* __restrict__ cb,
           float* __restrict__ out) {
    const int w = threadIdx.x >> 5, lane = threadIdx.x & 31;
    const int q = blockIdx.x * 8 + w;

    const int b = q >> 10, hw = q & 1023;
    const float* xcol = hidden + (size_t)b * (DIM * 1024) + hw;
    float xr[8];
    double fn = 0.0;
#pragma unroll
    for (int t = 0; t < 8; t++) {
        float v = xcol[(size_t)(lane * 8 + t) * 1024];
        xr[t] = v;
        fn += (double)v * (double)v;
    }
#pragma unroll
    for (int o = 16; o > 0; o >>= 1) fn += __shfl_xor_sync(~0u, fn, o);
    const float fn32 = (float)fn;

    int cnt = g_ccnt[q];
    if (cnt < 0) cnt = 0;
    if (cnt > CAP) cnt = CAP;
    const float2* cands = g_cand + (size_t)q * CAP;

    float bestR = 3.4e38f;
    int bestK = 0;
    for (int c = 0; c < cnt; c++) {
        int k = __float_as_int(cands[c].y) & (KC - 1);   // hard clamp
        const float4* er = (const float4*)(cb + (size_t)k * DIM + lane * 8);
        float4 e0 = er[0], e1 = er[1];
        float ev[8] = {e0.x, e0.y, e0.z, e0.w, e1.x, e1.y, e1.z, e1.w};
        double dot = 0.0, cnd = 0.0;
#pragma unroll
        for (int t = 0; t < 8; t++) {
            double ed = (double)ev[t];
            dot += (double)xr[t] * ed;
            cnd += ed * ed;
        }
#pragma unroll
        for (int o = 16; o > 0; o >>= 1) {
            dot += __shfl_xor_sync(~0u, dot, o);
            cnd += __shfl_xor_sync(~0u, cnd, o);
        }
        float t1 = __fsub_rn(fn32, __fmul_rn(2.0f, (float)dot));
        float R  = __fadd_rn(t1, (float)cnd);
        if (R < bestR || (R == bestR && k < bestK)) { bestR = R; bestK = k; }
    }
    if (lane == 0) {
        g_fin[q] = bestK;
        out[IDX_OFF + q] = (float)bestK;
    }
}

// ============================ output + loss ================================
__global__ void __launch_bounds__(256)
vq_output(const float* __restrict__ hidden, const float* __restrict__ cb,
          float* __restrict__ out) {
    __shared__ float Es[64 * 129];
    __shared__ int s_fin[128];
    __shared__ float lred[256];

    const int tid = threadIdx.x;
    const int qbase = blockIdx.x * BQ;
    const int b = qbase >> 10, hwbase = qbase & 1023;

    if (tid < 128) s_fin[tid] = g_fin[qbase + tid] & (KC - 1);   // hard clamp
    __syncthreads();

    const float* hsrc = hidden + (size_t)b * (DIM * 1024) + hwbase;
    float* obase = out + (size_t)b * (DIM * 1024) + hwbase;

    float lsum = 0.0f;
    for (int dchunk = 0; dchunk < 4; dchunk++) {
        const int dbase = dchunk * 64;
        for (int i = tid; i < 128 * 64; i += 256) {
            int qq = i >> 6, dd = i & 63;
            Es[dd * 129 + qq] = cb[(size_t)s_fin[qq] * DIM + dbase + dd];
        }
        __syncthreads();
        for (int i = tid; i < 64 * 128; i += 256) {
            int dd = i >> 7, qq = i & 127;
            int d = dbase + dd;
            float x = hsrc[(d << 10) + qq];
            float e = Es[dd * 129 + qq];
            float df = __fsub_rn(e, x);
            lsum += df * df;
            obase[(d << 10) + qq] = __fadd_rn(x, df);   // STE rounding
        }
        __syncthreads();
    }

    lred[tid] = lsum;
    __syncthreads();
    for (int s = 128; s > 0; s >>= 1) {
        if (tid < s) lred[tid] += lred[tid + s];
        __syncthreads();
    }
    if (tid == 0) atomicAdd(&g_loss, lred[0]);
}

__global__ void finalize_loss(float* __restrict__ out) {
    out[LOSS_OFF] = 1.25f * g_loss / (float)(NQ * DIM);
}

// ---------------------------------------------------------------------------
extern "C" void kernel_launch(void* const* d_in, const int* in_sizes, int n_in,
                              void* d_out, int out_size) {
    const float* hidden = (const float*)d_in[0];
    const float* cb     = (const float*)d_in[1];
    if (n_in >= 2 && in_sizes[0] == KC * DIM) {   // defensive input-order swap
        const float* t = hidden; hidden = cb; cb = t;
    }
    float* out = (float*)d_out;

    cudaFuncSetAttribute(vq_main, cudaFuncAttributeMaxDynamicSharedMemorySize,
                         SMEM_SZ);

    zero_loss_kernel<<<1, 1>>>();
    conv_hidden<<<dim3(32, 8, 16), dim3(32, 8)>>>(hidden);
    conv_cb<<<KC / 8, 256>>>(cb);
    vq_main<<<NQ / BQ, 256, SMEM_SZ>>>();
    vq_rescore<<<NQ / 8, 256>>>(hidden, cb, out);
    vq_output<<<NQ / BQ, 256>>>(hidden, cb, out);
    finalize_loss<<<1, 1>>>(out);
}